// round 4
// baseline (speedup 1.0000x reference)
#include <cuda_runtime.h>
#include <cuda_bf16.h>
#include <cstdint>

// Problem constants
#define B_SZ   4096
#define DIN    768
#define DOUT   512
#define Q_SZ   64
#define H1_SZ  32
#define H2_SZ  64
#define EPS    1e-5f

// GEMM1 split-K: K' = 3 * DIN
#define KSPLIT (3 * DIN)        // 2304
#define KC     64
#define NCH    (KSPLIT / KC)    // 36
#define GS     4
#define TILEB  16384
#define STAGEB (2 * TILEB)

// GEMM2 (G @ wo2) split-K: K2 = 3 * H2
#define K2     192
#define M2     32               // rows per CTA in gemm2_ln

// ---------------------------------------------------------------------------
// Static device scratch
// ---------------------------------------------------------------------------
__device__ __align__(256) float          g_xproj[B_SZ * DOUT];          // 8 MB
__device__ __align__(256) __nv_bfloat16  g_A[B_SZ * KSPLIT];            // 18.9 MB
__device__ __align__(256) __nv_bfloat16  g_Bt[DOUT * KSPLIT];           // 2.36 MB
__device__ __align__(256) __nv_bfloat16  g_G[B_SZ * K2];                // 1.5 MB
__device__ __align__(256) __nv_bfloat16  g_B2[DOUT * K2];               // 196 KB

// ---------------------------------------------------------------------------
// Helpers
// ---------------------------------------------------------------------------
__device__ __forceinline__ uint32_t smem_u32(const void* p) {
    uint32_t a;
    asm("{ .reg .u64 t; cvta.to.shared.u64 t, %1; cvt.u32.u64 %0, t; }"
        : "=r"(a) : "l"(p));
    return a;
}
__device__ __forceinline__ uint32_t swz(uint32_t off) {
    return off ^ ((off >> 3) & 0x70);
}
__device__ __forceinline__ void cpasync16(uint32_t dst, const void* src) {
    asm volatile("cp.async.cg.shared.global [%0], [%1], 16;"
                 :: "r"(dst), "l"(src) : "memory");
}
__device__ __forceinline__ void ldsm_x4(uint32_t* r, uint32_t addr) {
    asm volatile("ldmatrix.sync.aligned.m8n8.x4.shared.b16 {%0,%1,%2,%3}, [%4];"
                 : "=r"(r[0]), "=r"(r[1]), "=r"(r[2]), "=r"(r[3]) : "r"(addr));
}
__device__ __forceinline__ void ldsm_x2(uint32_t* r, uint32_t addr) {
    asm volatile("ldmatrix.sync.aligned.m8n8.x2.shared.b16 {%0,%1}, [%2];"
                 : "=r"(r[0]), "=r"(r[1]) : "r"(addr));
}
__device__ __forceinline__ void mma16816(float* d, const uint32_t* a, const uint32_t* b) {
    asm volatile(
        "mma.sync.aligned.m16n8k16.row.col.f32.bf16.bf16.f32 "
        "{%0,%1,%2,%3}, {%4,%5,%6,%7}, {%8,%9}, {%0,%1,%2,%3};"
        : "+f"(d[0]), "+f"(d[1]), "+f"(d[2]), "+f"(d[3])
        : "r"(a[0]), "r"(a[1]), "r"(a[2]), "r"(a[3]), "r"(b[0]), "r"(b[1]));
}

// ---------------------------------------------------------------------------
// Conversions for GEMM1 (fp32 -> bf16 hi/lo, 3-term fold)
// ---------------------------------------------------------------------------
__global__ void __launch_bounds__(256)
conv_x(const float* __restrict__ x, __nv_bfloat16* __restrict__ A)
{
    const int row = blockIdx.x;
    const float* xr = x + (long)row * DIN;
    __nv_bfloat16* Ar = A + (long)row * KSPLIT;
    #pragma unroll
    for (int i = 0; i < 3; i++) {
        const int k = threadIdx.x + i * 256;
        const float v = xr[k];
        const __nv_bfloat16 hi = __float2bfloat16(v);
        const __nv_bfloat16 lo = __float2bfloat16(v - __bfloat162float(hi));
        Ar[k]            = hi;
        Ar[k + DIN]      = hi;
        Ar[k + 2 * DIN]  = lo;
    }
}

__global__ void __launch_bounds__(256)
conv_w(const float* __restrict__ wp, __nv_bfloat16* __restrict__ Bt)
{
    __shared__ float t[32][33];
    const int k0 = blockIdx.x * 32, n0 = blockIdx.y * 32;
    const int tx = threadIdx.x & 31;
    const int ty = threadIdx.x >> 5;
    #pragma unroll
    for (int dy = 0; dy < 32; dy += 8)
        t[ty + dy][tx] = wp[(long)(k0 + ty + dy) * DOUT + n0 + tx];
    __syncthreads();
    #pragma unroll
    for (int dy = 0; dy < 32; dy += 8) {
        const int n = n0 + ty + dy, k = k0 + tx;
        const float v = t[tx][ty + dy];
        const __nv_bfloat16 hi = __float2bfloat16(v);
        const __nv_bfloat16 lo = __float2bfloat16(v - __bfloat162float(hi));
        __nv_bfloat16* Br = Bt + (long)n * KSPLIT;
        Br[k]           = hi;
        Br[k + DIN]     = lo;
        Br[k + 2 * DIN] = hi;
    }
}

// wo2 [H2, DOUT] -> B2 [DOUT][K2]: k<64:hi, 64..128:hi, 128..192:lo
__global__ void __launch_bounds__(256)
conv_wo2(const float* __restrict__ wo2, __nv_bfloat16* __restrict__ B2)
{
    const int n = blockIdx.x * 256 + threadIdx.x;
    __nv_bfloat16* Bn = B2 + (long)n * K2;
    #pragma unroll 8
    for (int k = 0; k < H2_SZ; k++) {
        const float v = wo2[k * DOUT + n];
        const __nv_bfloat16 hi = __float2bfloat16(v);
        const __nv_bfloat16 lo = __float2bfloat16(v - __bfloat162float(hi));
        Bn[k]       = hi;
        Bn[k + 64]  = hi;
        Bn[k + 128] = lo;
    }
}

// ---------------------------------------------------------------------------
// GEMM1 (unchanged from R3, passing): xproj = A' @ B'^T + bp
// ---------------------------------------------------------------------------
__global__ void __launch_bounds__(256, 1)
gemm_tc(const __nv_bfloat16* __restrict__ Ag, const __nv_bfloat16* __restrict__ Bg,
        const float* __restrict__ bias, float* __restrict__ C)
{
    extern __shared__ char dynsmem[];

    const int tid  = threadIdx.x;
    const int warp = tid >> 5, lane = tid & 31;
    const int wm = warp >> 2;
    const int wn = warp & 3;
    const int bn = blockIdx.x, bm = blockIdx.y;

    const uint32_t abase = (smem_u32(dynsmem) + 1023u) & ~1023u;

    const __nv_bfloat16* Atile = Ag + (long)(bm * 128) * KSPLIT;
    const __nv_bfloat16* Btile = Bg + (long)(bn * 128) * KSPLIT;

    auto load_chunk = [&](int c, int s) {
        const uint32_t sa = abase + s * STAGEB;
        const uint32_t sb = sa + TILEB;
        const int koff = c * KC;
        #pragma unroll
        for (int it = 0; it < 4; it++) {
            const int idx = it * 256 + tid;
            const int row = idx >> 3;
            const int c16 = idx & 7;
            const uint32_t soff = swz(row * 128 + c16 * 16);
            cpasync16(sa + soff, Atile + (long)row * KSPLIT + koff + c16 * 8);
            cpasync16(sb + soff, Btile + (long)row * KSPLIT + koff + c16 * 8);
        }
        asm volatile("cp.async.commit_group;" ::: "memory");
    };

    float acc[4][4][4];
    #pragma unroll
    for (int mt = 0; mt < 4; mt++)
        #pragma unroll
        for (int nt = 0; nt < 4; nt++)
            #pragma unroll
            for (int j = 0; j < 4; j++) acc[mt][nt][j] = 0.f;

    const uint32_t a_row = wm * 64 + (lane & 15);
    const uint32_t a_seg = (lane >> 4) * 16;
    const uint32_t b_row = wn * 32 + (lane & 7);
    const uint32_t b_seg = ((lane >> 3) & 1) * 16;

    #pragma unroll
    for (int c = 0; c < GS - 1; c++) load_chunk(c, c);

    for (int c = 0; c < NCH; c++) {
        asm volatile("cp.async.wait_group %0;" :: "n"(GS - 2) : "memory");
        __syncthreads();

        const int nl = c + GS - 1;
        if (nl < NCH) load_chunk(nl, nl & (GS - 1));

        const uint32_t sa = abase + (c & (GS - 1)) * STAGEB;
        const uint32_t sb = sa + TILEB;

        #pragma unroll
        for (int ks = 0; ks < 4; ks++) {
            uint32_t af[4][4], bf[4][2];
            #pragma unroll
            for (int mt = 0; mt < 4; mt++)
                ldsm_x4(af[mt], sa + swz((a_row + mt * 16) * 128 + ks * 32 + a_seg));
            #pragma unroll
            for (int nt = 0; nt < 4; nt++)
                ldsm_x2(bf[nt], sb + swz((b_row + nt * 8) * 128 + ks * 32 + b_seg));
            #pragma unroll
            for (int mt = 0; mt < 4; mt++)
                #pragma unroll
                for (int nt = 0; nt < 4; nt++)
                    mma16816(acc[mt][nt], af[mt], bf[nt]);
        }
    }

    const int g  = lane >> 2;
    const int tg = lane & 3;
    #pragma unroll
    for (int mt = 0; mt < 4; mt++) {
        const int m = bm * 128 + wm * 64 + mt * 16 + g;
        #pragma unroll
        for (int nt = 0; nt < 4; nt++) {
            const int n = bn * 128 + wn * 32 + nt * 8 + 2 * tg;
            const float b0 = bias[n], b1 = bias[n + 1];
            float2 v0, v1;
            v0.x = acc[mt][nt][0] + b0;  v0.y = acc[mt][nt][1] + b1;
            v1.x = acc[mt][nt][2] + b0;  v1.y = acc[mt][nt][3] + b1;
            *(float2*)(C + (long)m * DOUT + n)       = v0;
            *(float2*)(C + (long)(m + 8) * DOUT + n) = v1;
        }
    }
}

// ---------------------------------------------------------------------------
// kan_sug: stages B (relu-reduce), C (u), D (G), emit G as bf16 3-term split
// ---------------------------------------------------------------------------
#define ROWS 8

__global__ void __launch_bounds__(256)
kan_sug(const float* __restrict__ xproj,
        const float* __restrict__ wi1, const float* __restrict__ bi1,
        const float* __restrict__ wi2, const float* __restrict__ bi2,
        const float* __restrict__ wo1, const float* __restrict__ bo1,
        __nv_bfloat16* __restrict__ Gout)
{
    __shared__ float rows[ROWS][DOUT];
    __shared__ float Ssh[ROWS][H1_SZ];
    __shared__ float ush[ROWS][Q_SZ];
    __shared__ float Gsh[ROWS][H2_SZ];

    const int tid  = threadIdx.x;
    const int warp = tid >> 5;
    const int lane = tid & 31;
    const long base = (long)blockIdx.x * ROWS * DOUT;

    {
        const float4* src = (const float4*)(xproj + base);
        float4* dst = (float4*)(&rows[0][0]);
        #pragma unroll
        for (int i = 0; i < 4; i++) dst[tid + i * 256] = src[tid + i * 256];
    }
    __syncthreads();

    // Stage B
    {
        const float w1 = wi1[lane];
        const float b1 = bi1[lane];
        float s0 = 0.f, s1 = 0.f, s2 = 0.f, s3 = 0.f;
        const float4* rv = (const float4*)(&rows[warp][0]);
        #pragma unroll 4
        for (int d4 = 0; d4 < DOUT / 4; d4++) {
            const float4 v = rv[d4];
            s0 += fmaxf(fmaf(v.x, w1, b1), 0.f);
            s1 += fmaxf(fmaf(v.y, w1, b1), 0.f);
            s2 += fmaxf(fmaf(v.z, w1, b1), 0.f);
            s3 += fmaxf(fmaf(v.w, w1, b1), 0.f);
        }
        Ssh[warp][lane] = (s0 + s1) + (s2 + s3);
    }
    __syncthreads();

    // Stage C
    #pragma unroll
    for (int it = 0; it < 2; it++) {
        const int idx = tid + it * 256;
        const int r = idx >> 6, q = idx & 63;
        float acc = (float)DOUT * bi2[q];
        #pragma unroll
        for (int h = 0; h < H1_SZ; h++)
            acc = fmaf(Ssh[r][h], wi2[h * Q_SZ + q], acc);
        ush[r][q] = acc;
    }
    __syncthreads();

    // Stage D
    #pragma unroll
    for (int it = 0; it < 2; it++) {
        const int idx = tid + it * 256;
        const int r = idx >> 6, h2 = idx & 63;
        const float w = wo1[h2];
        const float b = bo1[h2];
        float g = 0.f;
        #pragma unroll
        for (int q = 0; q < Q_SZ; q++)
            g += fmaxf(fmaf(ush[r][q], w, b), 0.f);
        Gsh[r][h2] = g;
    }
    __syncthreads();

    // Emit G split: row-major [B_SZ][K2], cols 0-63 hi, 64-127 lo, 128-191 hi
    #pragma unroll
    for (int it = 0; it < 2; it++) {
        const int idx = tid + it * 256;
        const int r = idx >> 6, h2 = idx & 63;
        const float v = Gsh[r][h2];
        const __nv_bfloat16 hi = __float2bfloat16(v);
        const __nv_bfloat16 lo = __float2bfloat16(v - __bfloat162float(hi));
        __nv_bfloat16* Gr = Gout + (long)(blockIdx.x * ROWS + r) * K2;
        Gr[h2]       = hi;
        Gr[h2 + 64]  = lo;
        Gr[h2 + 128] = hi;
    }
}

// ---------------------------------------------------------------------------
// gemm2_ln: out = LayerNorm( G' @ B2^T + Q*bo2 ) * gamma + beta
// CTA: 32 rows x 512 cols (full N -> LN intra-CTA). 8 warps, warp = 32x64.
// ---------------------------------------------------------------------------
__global__ void __launch_bounds__(256, 1)
gemm2_ln(const __nv_bfloat16* __restrict__ Gb, const __nv_bfloat16* __restrict__ B2,
         const float* __restrict__ bo2, const float* __restrict__ gamma,
         const float* __restrict__ beta, float* __restrict__ out)
{
    __shared__ __align__(1024) char smA[3 * 4096];   // 3 chunks x 32 rows x 128B
    __shared__ float redS[M2][8], redQ[M2][8];
    __shared__ float muS[M2], invS[M2];

    const int tid  = threadIdx.x;
    const int warp = tid >> 5, lane = tid & 31;
    const int row0 = blockIdx.x * M2;
    const uint32_t sm = smem_u32(smA);

    // Load A (32 x 192 bf16) into 3 swizzled 64-col chunks
    #pragma unroll
    for (int i = 0; i < 3; i++) {
        const int u = tid + i * 256;            // 0..767
        const int c = u >> 8;
        const int r = (u >> 3) & 31;
        const int s = u & 7;
        cpasync16(sm + c * 4096 + swz(r * 128 + s * 16),
                  Gb + (long)(row0 + r) * K2 + c * 64 + s * 8);
    }
    asm volatile("cp.async.commit_group;" ::: "memory");
    asm volatile("cp.async.wait_group 0;" ::: "memory");
    __syncthreads();

    float acc[2][8][4];
    #pragma unroll
    for (int mt = 0; mt < 2; mt++)
        #pragma unroll
        for (int nt = 0; nt < 8; nt++)
            #pragma unroll
            for (int j = 0; j < 4; j++) acc[mt][nt][j] = 0.f;

    const uint32_t a_row = lane & 15;
    const uint32_t a_seg = (lane >> 4) * 16;
    const __nv_bfloat16* Bw = B2 + (long)(warp * 64) * K2;
    const int bln = lane >> 2;                   // n sub-offset within 8
    const int blk = (lane & 3) * 2;              // k offset

    #pragma unroll
    for (int kf = 0; kf < 12; kf++) {
        const int c = kf >> 2, ks = kf & 3;
        uint32_t af0[4], af1[4];
        ldsm_x4(af0, sm + c * 4096 + swz(a_row * 128 + ks * 32 + a_seg));
        ldsm_x4(af1, sm + c * 4096 + swz((a_row + 16) * 128 + ks * 32 + a_seg));
        #pragma unroll
        for (int nt = 0; nt < 8; nt++) {
            const __nv_bfloat16* bp = Bw + (long)(nt * 8 + bln) * K2 + kf * 16 + blk;
            uint32_t b[2];
            b[0] = *(const uint32_t*)bp;
            b[1] = *(const uint32_t*)(bp + 8);
            mma16816(acc[0][nt], af0, b);
            mma16816(acc[1][nt], af1, b);
        }
    }

    // Epilogue: +Q*bo2, LN stats, normalize, *gamma +beta
    const int g  = lane >> 2;
    const int tq = lane & 3;

    float rs[2][2] = {{0.f,0.f},{0.f,0.f}};
    float rq[2][2] = {{0.f,0.f},{0.f,0.f}};
    #pragma unroll
    for (int nt = 0; nt < 8; nt++) {
        const int n = warp * 64 + nt * 8 + 2 * tq;
        const float b0 = (float)Q_SZ * bo2[n];
        const float b1 = (float)Q_SZ * bo2[n + 1];
        #pragma unroll
        for (int mt = 0; mt < 2; mt++) {
            acc[mt][nt][0] += b0;  acc[mt][nt][1] += b1;
            acc[mt][nt][2] += b0;  acc[mt][nt][3] += b1;
            rs[mt][0] += acc[mt][nt][0] + acc[mt][nt][1];
            rq[mt][0] += acc[mt][nt][0]*acc[mt][nt][0] + acc[mt][nt][1]*acc[mt][nt][1];
            rs[mt][1] += acc[mt][nt][2] + acc[mt][nt][3];
            rq[mt][1] += acc[mt][nt][2]*acc[mt][nt][2] + acc[mt][nt][3]*acc[mt][nt][3];
        }
    }
    // reduce over the 4 lanes sharing a row (same l>>2)
    #pragma unroll
    for (int mt = 0; mt < 2; mt++)
        #pragma unroll
        for (int hf = 0; hf < 2; hf++) {
            #pragma unroll
            for (int off = 1; off < 4; off <<= 1) {
                rs[mt][hf] += __shfl_xor_sync(0xffffffffu, rs[mt][hf], off);
                rq[mt][hf] += __shfl_xor_sync(0xffffffffu, rq[mt][hf], off);
            }
            if (tq == 0) {
                const int r = mt * 16 + hf * 8 + g;
                redS[r][warp] = rs[mt][hf];
                redQ[r][warp] = rq[mt][hf];
            }
        }
    __syncthreads();

    if (tid < M2) {
        float s = 0.f, q2 = 0.f;
        #pragma unroll
        for (int w = 0; w < 8; w++) { s += redS[tid][w]; q2 += redQ[tid][w]; }
        const float mu  = s * (1.f / (float)DOUT);
        const float var = q2 * (1.f / (float)DOUT) - mu * mu;
        muS[tid]  = mu;
        invS[tid] = rsqrtf(var + EPS);
    }
    __syncthreads();

    #pragma unroll
    for (int nt = 0; nt < 8; nt++) {
        const int n = warp * 64 + nt * 8 + 2 * tq;
        const float ga0 = gamma[n], ga1 = gamma[n + 1];
        const float be0 = beta[n],  be1 = beta[n + 1];
        #pragma unroll
        for (int mt = 0; mt < 2; mt++) {
            const int r0 = mt * 16 + g;
            const int r1 = r0 + 8;
            float2 v0, v1;
            v0.x = (acc[mt][nt][0] - muS[r0]) * invS[r0] * ga0 + be0;
            v0.y = (acc[mt][nt][1] - muS[r0]) * invS[r0] * ga1 + be1;
            v1.x = (acc[mt][nt][2] - muS[r1]) * invS[r1] * ga0 + be0;
            v1.y = (acc[mt][nt][3] - muS[r1]) * invS[r1] * ga1 + be1;
            *(float2*)(out + (long)(row0 + r0) * DOUT + n) = v0;
            *(float2*)(out + (long)(row0 + r1) * DOUT + n) = v1;
        }
    }
}

// ---------------------------------------------------------------------------
// Launch
// ---------------------------------------------------------------------------
extern "C" void kernel_launch(void* const* d_in, const int* in_sizes, int n_in,
                              void* d_out, int out_size)
{
    const float* x     = (const float*)d_in[0];
    const float* wp    = (const float*)d_in[1];
    const float* bp    = (const float*)d_in[2];
    const float* wi1   = (const float*)d_in[3];
    const float* bi1   = (const float*)d_in[4];
    const float* wi2   = (const float*)d_in[5];
    const float* bi2   = (const float*)d_in[6];
    const float* wo1   = (const float*)d_in[7];
    const float* bo1   = (const float*)d_in[8];
    const float* wo2   = (const float*)d_in[9];
    const float* bo2   = (const float*)d_in[10];
    const float* gamma = (const float*)d_in[11];
    const float* beta  = (const float*)d_in[12];
    float* out = (float*)d_out;

    float* xproj;          cudaGetSymbolAddress((void**)&xproj, g_xproj);
    __nv_bfloat16* Ab;     cudaGetSymbolAddress((void**)&Ab, g_A);
    __nv_bfloat16* Bb;     cudaGetSymbolAddress((void**)&Bb, g_Bt);
    __nv_bfloat16* Gb;     cudaGetSymbolAddress((void**)&Gb, g_G);
    __nv_bfloat16* B2b;    cudaGetSymbolAddress((void**)&B2b, g_B2);

    conv_x<<<B_SZ, 256>>>(x, Ab);
    conv_w<<<dim3(DIN / 32, DOUT / 32), 256>>>(wp, Bb);
    conv_wo2<<<DOUT / 256, 256>>>(wo2, B2b);

    const int dyn = GS * STAGEB + 1024;
    cudaFuncSetAttribute(gemm_tc, cudaFuncAttributeMaxDynamicSharedMemorySize, dyn);
    gemm_tc<<<dim3(DOUT / 128, B_SZ / 128), 256, dyn>>>(Ab, Bb, bp, xproj);

    kan_sug<<<B_SZ / ROWS, 256>>>(xproj, wi1, bi1, wi2, bi2, wo1, bo1, Gb);

    gemm2_ln<<<B_SZ / M2, 256>>>(Gb, B2b, bo2, gamma, beta, out);
}

// round 5
// speedup vs baseline: 2.0281x; 2.0281x over previous
#include <cuda_runtime.h>
#include <cuda_bf16.h>
#include <cstdint>

// Problem constants
#define B_SZ   4096
#define DIN    768
#define DOUT   512
#define Q_SZ   64
#define H1_SZ  32
#define H2_SZ  64
#define EPS    1e-5f

// GEMM1 split-K: K' = 3 * DIN, split across 2 CTAs in z
#define KSPLIT (3 * DIN)        // 2304
#define KC     64
#define NCHH   (KSPLIT / KC / 2)  // 18 chunks per K-half
#define GS     3                  // pipeline stages
#define TILEB  16384              // one 128x64 bf16 tile
#define STAGEB (2 * TILEB)

// ---------------------------------------------------------------------------
// Static device scratch
// ---------------------------------------------------------------------------
__device__ __align__(256) float          g_xp[2][B_SZ * DOUT];          // 16 MB partials
__device__ __align__(256) __nv_bfloat16  g_A[B_SZ * KSPLIT];            // 18.9 MB
__device__ __align__(256) __nv_bfloat16  g_Bt[DOUT * KSPLIT];           // 2.36 MB

// ---------------------------------------------------------------------------
// Helpers
// ---------------------------------------------------------------------------
__device__ __forceinline__ uint32_t smem_u32(const void* p) {
    uint32_t a;
    asm("{ .reg .u64 t; cvta.to.shared.u64 t, %1; cvt.u32.u64 %0, t; }"
        : "=r"(a) : "l"(p));
    return a;
}
__device__ __forceinline__ uint32_t swz(uint32_t off) {
    return off ^ ((off >> 3) & 0x70);
}
__device__ __forceinline__ void cpasync16(uint32_t dst, const void* src) {
    asm volatile("cp.async.cg.shared.global [%0], [%1], 16;"
                 :: "r"(dst), "l"(src) : "memory");
}
__device__ __forceinline__ void ldsm_x4(uint32_t* r, uint32_t addr) {
    asm volatile("ldmatrix.sync.aligned.m8n8.x4.shared.b16 {%0,%1,%2,%3}, [%4];"
                 : "=r"(r[0]), "=r"(r[1]), "=r"(r[2]), "=r"(r[3]) : "r"(addr));
}
__device__ __forceinline__ void ldsm_x2(uint32_t* r, uint32_t addr) {
    asm volatile("ldmatrix.sync.aligned.m8n8.x2.shared.b16 {%0,%1}, [%2];"
                 : "=r"(r[0]), "=r"(r[1]) : "r"(addr));
}
__device__ __forceinline__ void mma16816(float* d, const uint32_t* a, const uint32_t* b) {
    asm volatile(
        "mma.sync.aligned.m16n8k16.row.col.f32.bf16.bf16.f32 "
        "{%0,%1,%2,%3}, {%4,%5,%6,%7}, {%8,%9}, {%0,%1,%2,%3};"
        : "+f"(d[0]), "+f"(d[1]), "+f"(d[2]), "+f"(d[3])
        : "r"(a[0]), "r"(a[1]), "r"(a[2]), "r"(a[3]), "r"(b[0]), "r"(b[1]));
}

// ---------------------------------------------------------------------------
// Conversions (fp32 -> bf16 hi/lo, 3-term fold into K)
// ---------------------------------------------------------------------------
__global__ void __launch_bounds__(256)
conv_x(const float* __restrict__ x, __nv_bfloat16* __restrict__ A)
{
    const int row = blockIdx.x;
    const float* xr = x + (long)row * DIN;
    __nv_bfloat16* Ar = A + (long)row * KSPLIT;
    #pragma unroll
    for (int i = 0; i < 3; i++) {
        const int k = threadIdx.x + i * 256;
        const float v = xr[k];
        const __nv_bfloat16 hi = __float2bfloat16(v);
        const __nv_bfloat16 lo = __float2bfloat16(v - __bfloat162float(hi));
        Ar[k]            = hi;
        Ar[k + DIN]      = hi;
        Ar[k + 2 * DIN]  = lo;
    }
}

__global__ void __launch_bounds__(256)
conv_w(const float* __restrict__ wp, __nv_bfloat16* __restrict__ Bt)
{
    __shared__ float t[32][33];
    const int k0 = blockIdx.x * 32, n0 = blockIdx.y * 32;
    const int tx = threadIdx.x & 31;
    const int ty = threadIdx.x >> 5;
    #pragma unroll
    for (int dy = 0; dy < 32; dy += 8)
        t[ty + dy][tx] = wp[(long)(k0 + ty + dy) * DOUT + n0 + tx];
    __syncthreads();
    #pragma unroll
    for (int dy = 0; dy < 32; dy += 8) {
        const int n = n0 + ty + dy, k = k0 + tx;
        const float v = t[tx][ty + dy];
        const __nv_bfloat16 hi = __float2bfloat16(v);
        const __nv_bfloat16 lo = __float2bfloat16(v - __bfloat162float(hi));
        __nv_bfloat16* Br = Bt + (long)n * KSPLIT;
        Br[k]           = hi;
        Br[k + DIN]     = lo;
        Br[k + 2 * DIN] = hi;
    }
}

// ---------------------------------------------------------------------------
// GEMM1, split-K=2: Cp[z] = A'[:,zK/2:(z+1)K/2] @ B'^T slice.
// 128x128 CTA tile, 8 warps (2m x 4n), GS=3 cp.async pipeline, 2 CTAs/SM.
// ---------------------------------------------------------------------------
__global__ void __launch_bounds__(256, 2)
gemm_tc(const __nv_bfloat16* __restrict__ Ag, const __nv_bfloat16* __restrict__ Bg,
        float* __restrict__ Cbase)
{
    extern __shared__ char dynsmem[];

    const int tid  = threadIdx.x;
    const int warp = tid >> 5, lane = tid & 31;
    const int wm = warp >> 2;
    const int wn = warp & 3;
    const int bn = blockIdx.x, bm = blockIdx.y, kz = blockIdx.z;

    const uint32_t abase = (smem_u32(dynsmem) + 1023u) & ~1023u;

    const __nv_bfloat16* Atile = Ag + (long)(bm * 128) * KSPLIT;
    const __nv_bfloat16* Btile = Bg + (long)(bn * 128) * KSPLIT;
    float* C = Cbase + (long)kz * (B_SZ * DOUT);
    const int kbase = kz * (NCHH * KC);

    auto load_chunk = [&](int c, int s) {
        const uint32_t sa = abase + s * STAGEB;
        const uint32_t sb = sa + TILEB;
        const int koff = kbase + c * KC;
        #pragma unroll
        for (int it = 0; it < 4; it++) {
            const int idx = it * 256 + tid;
            const int row = idx >> 3;
            const int c16 = idx & 7;
            const uint32_t soff = swz(row * 128 + c16 * 16);
            cpasync16(sa + soff, Atile + (long)row * KSPLIT + koff + c16 * 8);
            cpasync16(sb + soff, Btile + (long)row * KSPLIT + koff + c16 * 8);
        }
        asm volatile("cp.async.commit_group;" ::: "memory");
    };

    float acc[4][4][4];
    #pragma unroll
    for (int mt = 0; mt < 4; mt++)
        #pragma unroll
        for (int nt = 0; nt < 4; nt++)
            #pragma unroll
            for (int j = 0; j < 4; j++) acc[mt][nt][j] = 0.f;

    const uint32_t a_row = wm * 64 + (lane & 15);
    const uint32_t a_seg = (lane >> 4) * 16;
    const uint32_t b_row = wn * 32 + (lane & 7);
    const uint32_t b_seg = ((lane >> 3) & 1) * 16;

    // prologue: 2 chunks in flight
    load_chunk(0, 0);
    load_chunk(1, 1);

    int s_cons = 0, s_load = 2;
    for (int c = 0; c < NCHH; c++) {
        asm volatile("cp.async.wait_group %0;" :: "n"(GS - 2) : "memory");
        __syncthreads();

        const int nl = c + GS - 1;
        if (nl < NCHH) load_chunk(nl, s_load);
        if (++s_load == GS) s_load = 0;

        const uint32_t sa = abase + s_cons * STAGEB;
        const uint32_t sb = sa + TILEB;
        if (++s_cons == GS) s_cons = 0;

        #pragma unroll
        for (int ks = 0; ks < 4; ks++) {
            uint32_t af[4][4], bf[4][2];
            #pragma unroll
            for (int mt = 0; mt < 4; mt++)
                ldsm_x4(af[mt], sa + swz((a_row + mt * 16) * 128 + ks * 32 + a_seg));
            #pragma unroll
            for (int nt = 0; nt < 4; nt++)
                ldsm_x2(bf[nt], sb + swz((b_row + nt * 8) * 128 + ks * 32 + b_seg));
            #pragma unroll
            for (int mt = 0; mt < 4; mt++)
                #pragma unroll
                for (int nt = 0; nt < 4; nt++)
                    mma16816(acc[mt][nt], af[mt], bf[nt]);
        }
    }

    // epilogue: store partials (bias added in kan_fused)
    const int g  = lane >> 2;
    const int tg = lane & 3;
    #pragma unroll
    for (int mt = 0; mt < 4; mt++) {
        const int m = bm * 128 + wm * 64 + mt * 16 + g;
        #pragma unroll
        for (int nt = 0; nt < 4; nt++) {
            const int n = bn * 128 + wn * 32 + nt * 8 + 2 * tg;
            float2 v0, v1;
            v0.x = acc[mt][nt][0];  v0.y = acc[mt][nt][1];
            v1.x = acc[mt][nt][2];  v1.y = acc[mt][nt][3];
            *(float2*)(C + (long)m * DOUT + n)       = v0;
            *(float2*)(C + (long)(m + 8) * DOUT + n) = v1;
        }
    }
}

// ---------------------------------------------------------------------------
// Kernel 2: fused  (p0+p1+bias) -> S -> u -> G -> (G@wo2 + Q*bo2) -> LayerNorm
// ---------------------------------------------------------------------------
#define ROWS 8

__global__ void __launch_bounds__(256)
kan_fused(const float* __restrict__ xp0, const float* __restrict__ xp1,
          const float* __restrict__ bp,
          const float* __restrict__ wi1, const float* __restrict__ bi1,
          const float* __restrict__ wi2, const float* __restrict__ bi2,
          const float* __restrict__ wo1, const float* __restrict__ bo1,
          const float* __restrict__ wo2, const float* __restrict__ bo2,
          const float* __restrict__ gamma, const float* __restrict__ beta,
          float* __restrict__ out)
{
    __shared__ float rows[ROWS][DOUT];
    __shared__ float Ssh[ROWS][H1_SZ];
    __shared__ float ush[ROWS][Q_SZ];
    __shared__ float Gsh[ROWS][H2_SZ];
    __shared__ float red[ROWS][8][2];

    const int tid  = threadIdx.x;
    const int warp = tid >> 5;
    const int lane = tid & 31;
    const long base = (long)blockIdx.x * ROWS * DOUT;

    {
        const float4* s0 = (const float4*)(xp0 + base);
        const float4* s1 = (const float4*)(xp1 + base);
        const float4* bb = (const float4*)bp;
        float4* dst = (float4*)(&rows[0][0]);
        #pragma unroll
        for (int i = 0; i < 4; i++) {
            const int j = tid + i * 256;
            const float4 a = s0[j];
            const float4 b = s1[j];
            const float4 c = bb[j & 127];
            float4 o;
            o.x = a.x + b.x + c.x;
            o.y = a.y + b.y + c.y;
            o.z = a.z + b.z + c.z;
            o.w = a.w + b.w + c.w;
            dst[j] = o;
        }
    }
    __syncthreads();

    // Stage B
    {
        const float w1 = wi1[lane];
        const float b1 = bi1[lane];
        float s0 = 0.f, s1 = 0.f, s2 = 0.f, s3 = 0.f;
        const float4* rv = (const float4*)(&rows[warp][0]);
        #pragma unroll 4
        for (int d4 = 0; d4 < DOUT / 4; d4++) {
            const float4 v = rv[d4];
            s0 += fmaxf(fmaf(v.x, w1, b1), 0.f);
            s1 += fmaxf(fmaf(v.y, w1, b1), 0.f);
            s2 += fmaxf(fmaf(v.z, w1, b1), 0.f);
            s3 += fmaxf(fmaf(v.w, w1, b1), 0.f);
        }
        Ssh[warp][lane] = (s0 + s1) + (s2 + s3);
    }
    __syncthreads();

    // Stage C
    #pragma unroll
    for (int it = 0; it < 2; it++) {
        const int idx = tid + it * 256;
        const int r = idx >> 6, q = idx & 63;
        float acc = (float)DOUT * bi2[q];
        #pragma unroll
        for (int h = 0; h < H1_SZ; h++)
            acc = fmaf(Ssh[r][h], wi2[h * Q_SZ + q], acc);
        ush[r][q] = acc;
    }
    __syncthreads();

    // Stage D
    #pragma unroll
    for (int it = 0; it < 2; it++) {
        const int idx = tid + it * 256;
        const int r = idx >> 6, h2 = idx & 63;
        const float w = wo1[h2];
        const float b = bo1[h2];
        float g = 0.f;
        #pragma unroll
        for (int q = 0; q < Q_SZ; q++)
            g += fmaxf(fmaf(ush[r][q], w, b), 0.f);
        Gsh[r][h2] = g;
    }
    __syncthreads();

    // Stage E
    const int d0 = tid;
    const int d1 = tid + 256;
    float acc0[ROWS], acc1[ROWS];
    #pragma unroll
    for (int r = 0; r < ROWS; r++) { acc0[r] = 0.f; acc1[r] = 0.f; }

    #pragma unroll 4
    for (int h2 = 0; h2 < H2_SZ; h2++) {
        const float w0  = wo2[h2 * DOUT + d0];
        const float w1v = wo2[h2 * DOUT + d1];
        #pragma unroll
        for (int r = 0; r < ROWS; r++) {
            const float g = Gsh[r][h2];
            acc0[r] = fmaf(g, w0, acc0[r]);
            acc1[r] = fmaf(g, w1v, acc1[r]);
        }
    }
    {
        const float bb0 = (float)Q_SZ * bo2[d0];
        const float bb1 = (float)Q_SZ * bo2[d1];
        #pragma unroll
        for (int r = 0; r < ROWS; r++) { acc0[r] += bb0; acc1[r] += bb1; }
    }

    #pragma unroll
    for (int r = 0; r < ROWS; r++) {
        float ps = acc0[r] + acc1[r];
        float pq = acc0[r] * acc0[r] + acc1[r] * acc1[r];
        #pragma unroll
        for (int off = 16; off > 0; off >>= 1) {
            ps += __shfl_xor_sync(0xffffffffu, ps, off);
            pq += __shfl_xor_sync(0xffffffffu, pq, off);
        }
        if (lane == 0) { red[r][warp][0] = ps; red[r][warp][1] = pq; }
    }
    __syncthreads();

    const float g0 = gamma[d0], g1 = gamma[d1];
    const float be0 = beta[d0], be1 = beta[d1];
    #pragma unroll
    for (int r = 0; r < ROWS; r++) {
        float s = 0.f, q2 = 0.f;
        #pragma unroll
        for (int w = 0; w < 8; w++) { s += red[r][w][0]; q2 += red[r][w][1]; }
        const float mu  = s * (1.f / (float)DOUT);
        const float var = q2 * (1.f / (float)DOUT) - mu * mu;
        const float inv = rsqrtf(var + EPS);
        const long ob = base + (long)r * DOUT;
        out[ob + d0] = (acc0[r] - mu) * inv * g0 + be0;
        out[ob + d1] = (acc1[r] - mu) * inv * g1 + be1;
    }
}

// ---------------------------------------------------------------------------
// Launch
// ---------------------------------------------------------------------------
extern "C" void kernel_launch(void* const* d_in, const int* in_sizes, int n_in,
                              void* d_out, int out_size)
{
    const float* x     = (const float*)d_in[0];
    const float* wp    = (const float*)d_in[1];
    const float* bp    = (const float*)d_in[2];
    const float* wi1   = (const float*)d_in[3];
    const float* bi1   = (const float*)d_in[4];
    const float* wi2   = (const float*)d_in[5];
    const float* bi2   = (const float*)d_in[6];
    const float* wo1   = (const float*)d_in[7];
    const float* bo1   = (const float*)d_in[8];
    const float* wo2   = (const float*)d_in[9];
    const float* bo2   = (const float*)d_in[10];
    const float* gamma = (const float*)d_in[11];
    const float* beta  = (const float*)d_in[12];
    float* out = (float*)d_out;

    float* xp;             cudaGetSymbolAddress((void**)&xp, g_xp);
    __nv_bfloat16* Ab;     cudaGetSymbolAddress((void**)&Ab, g_A);
    __nv_bfloat16* Bb;     cudaGetSymbolAddress((void**)&Bb, g_Bt);

    conv_x<<<B_SZ, 256>>>(x, Ab);
    conv_w<<<dim3(DIN / 32, DOUT / 32), 256>>>(wp, Bb);

    const int dyn = GS * STAGEB + 1024;   // ~97 KB
    cudaFuncSetAttribute(gemm_tc, cudaFuncAttributeMaxDynamicSharedMemorySize, dyn);
    gemm_tc<<<dim3(DOUT / 128, B_SZ / 128, 2), 256, dyn>>>(Ab, Bb, xp);

    kan_fused<<<B_SZ / ROWS, 256>>>(xp, xp + (long)B_SZ * DOUT, bp,
                                    wi1, bi1, wi2, bi2,
                                    wo1, bo1, wo2, bo2, gamma, beta, out);
}

// round 6
// speedup vs baseline: 2.1556x; 1.0629x over previous
#include <cuda_runtime.h>
#include <cuda_bf16.h>
#include <cstdint>

// Problem constants
#define B_SZ   4096
#define DIN    768
#define DOUT   512
#define Q_SZ   64
#define H1_SZ  32
#define H2_SZ  64
#define EPS    1e-5f

// GEMM1 split-K: K' = 3 * DIN, split across 2 CTAs in z
#define KSPLIT (3 * DIN)          // 2304
#define KC     64
#define NCHH   (KSPLIT / KC / 2)  // 18 chunks per K-half
#define GS     3                  // pipeline stages
#define TILEB  16384              // one 128x64 bf16 tile
#define STAGEB (2 * TILEB)

// ---------------------------------------------------------------------------
// Static device scratch
// ---------------------------------------------------------------------------
__device__ __align__(256) float          g_xp[2][B_SZ * DOUT];          // 16 MB partials
__device__ __align__(256) __nv_bfloat16  g_A[B_SZ * KSPLIT];            // 18.9 MB
__device__ __align__(256) __nv_bfloat16  g_Bt[DOUT * KSPLIT];           // 2.36 MB

// ---------------------------------------------------------------------------
// Helpers
// ---------------------------------------------------------------------------
__device__ __forceinline__ uint32_t smem_u32(const void* p) {
    uint32_t a;
    asm("{ .reg .u64 t; cvta.to.shared.u64 t, %1; cvt.u32.u64 %0, t; }"
        : "=r"(a) : "l"(p));
    return a;
}
__device__ __forceinline__ uint32_t swz(uint32_t off) {
    return off ^ ((off >> 3) & 0x70);
}
__device__ __forceinline__ void cpasync16(uint32_t dst, const void* src) {
    asm volatile("cp.async.cg.shared.global [%0], [%1], 16;"
                 :: "r"(dst), "l"(src) : "memory");
}
__device__ __forceinline__ void ldsm_x4(uint32_t* r, uint32_t addr) {
    asm volatile("ldmatrix.sync.aligned.m8n8.x4.shared.b16 {%0,%1,%2,%3}, [%4];"
                 : "=r"(r[0]), "=r"(r[1]), "=r"(r[2]), "=r"(r[3]) : "r"(addr));
}
__device__ __forceinline__ void ldsm_x2(uint32_t* r, uint32_t addr) {
    asm volatile("ldmatrix.sync.aligned.m8n8.x2.shared.b16 {%0,%1}, [%2];"
                 : "=r"(r[0]), "=r"(r[1]) : "r"(addr));
}
__device__ __forceinline__ void mma16816(float* d, const uint32_t* a, const uint32_t* b) {
    asm volatile(
        "mma.sync.aligned.m16n8k16.row.col.f32.bf16.bf16.f32 "
        "{%0,%1,%2,%3}, {%4,%5,%6,%7}, {%8,%9}, {%0,%1,%2,%3};"
        : "+f"(d[0]), "+f"(d[1]), "+f"(d[2]), "+f"(d[3])
        : "r"(a[0]), "r"(a[1]), "r"(a[2]), "r"(a[3]), "r"(b[0]), "r"(b[1]));
}

// ---------------------------------------------------------------------------
// Conversions (fp32 -> bf16 hi/lo, 3-term fold into K)
// ---------------------------------------------------------------------------
__global__ void __launch_bounds__(256)
conv_x(const float* __restrict__ x, __nv_bfloat16* __restrict__ A)
{
    const int row = blockIdx.x;
    const float* xr = x + (long)row * DIN;
    __nv_bfloat16* Ar = A + (long)row * KSPLIT;
    #pragma unroll
    for (int i = 0; i < 3; i++) {
        const int k = threadIdx.x + i * 256;
        const float v = xr[k];
        const __nv_bfloat16 hi = __float2bfloat16(v);
        const __nv_bfloat16 lo = __float2bfloat16(v - __bfloat162float(hi));
        Ar[k]            = hi;
        Ar[k + DIN]      = hi;
        Ar[k + 2 * DIN]  = lo;
    }
}

__global__ void __launch_bounds__(256)
conv_w(const float* __restrict__ wp, __nv_bfloat16* __restrict__ Bt)
{
    __shared__ float t[32][33];
    const int k0 = blockIdx.x * 32, n0 = blockIdx.y * 32;
    const int tx = threadIdx.x & 31;
    const int ty = threadIdx.x >> 5;
    #pragma unroll
    for (int dy = 0; dy < 32; dy += 8)
        t[ty + dy][tx] = wp[(long)(k0 + ty + dy) * DOUT + n0 + tx];
    __syncthreads();
    #pragma unroll
    for (int dy = 0; dy < 32; dy += 8) {
        const int n = n0 + ty + dy, k = k0 + tx;
        const float v = t[tx][ty + dy];
        const __nv_bfloat16 hi = __float2bfloat16(v);
        const __nv_bfloat16 lo = __float2bfloat16(v - __bfloat162float(hi));
        __nv_bfloat16* Br = Bt + (long)n * KSPLIT;
        Br[k]           = hi;
        Br[k + DIN]     = lo;
        Br[k + 2 * DIN] = hi;
    }
}

// ---------------------------------------------------------------------------
// GEMM1, split-K=2: low register pressure so 2 CTAs/SM is real (no spills).
// ---------------------------------------------------------------------------
__global__ void __launch_bounds__(256, 2)
gemm_tc(const __nv_bfloat16* __restrict__ Ag, const __nv_bfloat16* __restrict__ Bg,
        float* __restrict__ Cbase)
{
    extern __shared__ char dynsmem[];

    const int tid  = threadIdx.x;
    const int warp = tid >> 5, lane = tid & 31;
    const int wm = warp >> 2;
    const int wn = warp & 3;
    const int bn = blockIdx.x, bm = blockIdx.y, kz = blockIdx.z;

    const uint32_t abase = (smem_u32(dynsmem) + 1023u) & ~1023u;

    const __nv_bfloat16* Atile = Ag + (long)(bm * 128) * KSPLIT;
    const __nv_bfloat16* Btile = Bg + (long)(bn * 128) * KSPLIT;
    float* C = Cbase + (long)kz * (B_SZ * DOUT);
    const int kbase = kz * (NCHH * KC);

    auto load_chunk = [&](int c, int s) {
        const uint32_t sa = abase + s * STAGEB;
        const uint32_t sb = sa + TILEB;
        const int koff = kbase + c * KC;
        #pragma unroll
        for (int it = 0; it < 4; it++) {
            const int idx = it * 256 + tid;
            const int row = idx >> 3;
            const int c16 = idx & 7;
            const uint32_t soff = swz(row * 128 + c16 * 16);
            cpasync16(sa + soff, Atile + (long)row * KSPLIT + koff + c16 * 8);
            cpasync16(sb + soff, Btile + (long)row * KSPLIT + koff + c16 * 8);
        }
        asm volatile("cp.async.commit_group;" ::: "memory");
    };

    float acc[4][4][4];
    #pragma unroll
    for (int mt = 0; mt < 4; mt++)
        #pragma unroll
        for (int nt = 0; nt < 4; nt++)
            #pragma unroll
            for (int j = 0; j < 4; j++) acc[mt][nt][j] = 0.f;

    const uint32_t a_row = wm * 64 + (lane & 15);
    const uint32_t a_seg = (lane >> 4) * 16;
    const uint32_t b_row = wn * 32 + (lane & 7);
    const uint32_t b_seg = ((lane >> 3) & 1) * 16;

    load_chunk(0, 0);
    load_chunk(1, 1);

    int s_cons = 0, s_load = 2;
    for (int c = 0; c < NCHH; c++) {
        asm volatile("cp.async.wait_group %0;" :: "n"(GS - 2) : "memory");
        __syncthreads();

        const int nl = c + GS - 1;
        if (nl < NCHH) load_chunk(nl, s_load);
        if (++s_load == GS) s_load = 0;

        const uint32_t sa = abase + s_cons * STAGEB;
        const uint32_t sb = sa + TILEB;
        if (++s_cons == GS) s_cons = 0;

        // low-reg inner loop: bf per ks, af per mt
        #pragma unroll
        for (int ks = 0; ks < 4; ks++) {
            uint32_t bf[4][2];
            #pragma unroll
            for (int nt = 0; nt < 4; nt++)
                ldsm_x2(bf[nt], sb + swz((b_row + nt * 8) * 128 + ks * 32 + b_seg));
            #pragma unroll
            for (int mt = 0; mt < 4; mt++) {
                uint32_t af[4];
                ldsm_x4(af, sa + swz((a_row + mt * 16) * 128 + ks * 32 + a_seg));
                #pragma unroll
                for (int nt = 0; nt < 4; nt++)
                    mma16816(acc[mt][nt], af, bf[nt]);
            }
        }
    }

    const int g  = lane >> 2;
    const int tg = lane & 3;
    #pragma unroll
    for (int mt = 0; mt < 4; mt++) {
        const int m = bm * 128 + wm * 64 + mt * 16 + g;
        #pragma unroll
        for (int nt = 0; nt < 4; nt++) {
            const int n = bn * 128 + wn * 32 + nt * 8 + 2 * tg;
            float2 v0, v1;
            v0.x = acc[mt][nt][0];  v0.y = acc[mt][nt][1];
            v1.x = acc[mt][nt][2];  v1.y = acc[mt][nt][3];
            *(float2*)(C + (long)m * DOUT + n)       = v0;
            *(float2*)(C + (long)(m + 8) * DOUT + n) = v1;
        }
    }
}

// ---------------------------------------------------------------------------
// Kernel 2: fused  (p0+p1+bias) -> S -> u -> G -> (G@wo2 + Q*bo2) -> LayerNorm
// ---------------------------------------------------------------------------
#define ROWS 8

__global__ void __launch_bounds__(256)
kan_fused(const float* __restrict__ xp0, const float* __restrict__ xp1,
          const float* __restrict__ bp,
          const float* __restrict__ wi1, const float* __restrict__ bi1,
          const float* __restrict__ wi2, const float* __restrict__ bi2,
          const float* __restrict__ wo1, const float* __restrict__ bo1,
          const float* __restrict__ wo2, const float* __restrict__ bo2,
          const float* __restrict__ gamma, const float* __restrict__ beta,
          float* __restrict__ out)
{
    __shared__ float rows[ROWS][DOUT];
    __shared__ float Ssh[ROWS][H1_SZ];
    __shared__ float ush[ROWS][Q_SZ];
    __shared__ float GshT[H2_SZ][ROWS];     // transposed: [h2][r]
    __shared__ float red[ROWS][8][2];

    const int tid  = threadIdx.x;
    const int warp = tid >> 5;
    const int lane = tid & 31;
    const long base = (long)blockIdx.x * ROWS * DOUT;

    // Load 8 rows: xp0 + xp1 + bias
    {
        const float4* s0 = (const float4*)(xp0 + base);
        const float4* s1 = (const float4*)(xp1 + base);
        const float4* bb = (const float4*)bp;
        float4* dst = (float4*)(&rows[0][0]);
        #pragma unroll
        for (int i = 0; i < 4; i++) {
            const int j = tid + i * 256;
            const float4 a = s0[j];
            const float4 b = s1[j];
            const float4 c = bb[j & 127];
            float4 o;
            o.x = a.x + b.x + c.x;
            o.y = a.y + b.y + c.y;
            o.z = a.z + b.z + c.z;
            o.w = a.w + b.w + c.w;
            dst[j] = o;
        }
    }
    __syncthreads();

    // Stage B: S[r][h] = sum_d relu(v*w+b) = 0.5*(w*V + 512*b + sum|v*w+b|)
    {
        // per-warp row sum V
        float vs = 0.f;
        const float4* rv = (const float4*)(&rows[warp][0]);
        #pragma unroll
        for (int i = 0; i < 4; i++) {
            const float4 v = rv[lane + i * 32];
            vs += (v.x + v.y) + (v.z + v.w);
        }
        #pragma unroll
        for (int off = 16; off > 0; off >>= 1)
            vs += __shfl_xor_sync(0xffffffffu, vs, off);

        const float w1 = wi1[lane];
        const float b1 = bi1[lane];
        float s0 = 0.f, s1 = 0.f, s2 = 0.f, s3 = 0.f;
        #pragma unroll 4
        for (int d4 = 0; d4 < DOUT / 4; d4++) {
            const float4 v = rv[d4];
            s0 += fabsf(fmaf(v.x, w1, b1));   // FADD with |abs| modifier
            s1 += fabsf(fmaf(v.y, w1, b1));
            s2 += fabsf(fmaf(v.z, w1, b1));
            s3 += fabsf(fmaf(v.w, w1, b1));
        }
        const float sabs = (s0 + s1) + (s2 + s3);
        Ssh[warp][lane] = 0.5f * (fmaf(w1, vs, (float)DOUT * b1) + sabs);
    }
    __syncthreads();

    // Stage C: u[r][q]
    #pragma unroll
    for (int it = 0; it < 2; it++) {
        const int idx = tid + it * 256;
        const int r = idx >> 6, q = idx & 63;
        float acc = (float)DOUT * bi2[q];
        #pragma unroll
        for (int h = 0; h < H1_SZ; h++)
            acc = fmaf(Ssh[r][h], wi2[h * Q_SZ + q], acc);
        ush[r][q] = acc;
    }
    __syncthreads();

    // Stage D: G[r][h2] -> stored transposed
    #pragma unroll
    for (int it = 0; it < 2; it++) {
        const int idx = tid + it * 256;
        const int r = idx >> 6, h2 = idx & 63;
        const float w = wo1[h2];
        const float b = bo1[h2];
        float g = 0.f;
        #pragma unroll
        for (int q = 0; q < Q_SZ; q++)
            g += fmaxf(fmaf(ush[r][q], w, b), 0.f);
        GshT[h2][r] = g;
    }
    __syncthreads();

    // Stage E: summed[r][d] = sum_h2 G[r][h2]*wo2[h2][d] + Q*bo2[d]
    // each thread: 2 adjacent cols; G via LDS.128 broadcast.
    const int d0 = tid * 2;
    float ax[ROWS], ay[ROWS];
    #pragma unroll
    for (int r = 0; r < ROWS; r++) { ax[r] = 0.f; ay[r] = 0.f; }

    #pragma unroll 4
    for (int h2 = 0; h2 < H2_SZ; h2++) {
        const float2 w = *(const float2*)(wo2 + h2 * DOUT + d0);   // LDG.64 coalesced
        const float4 ga = *(const float4*)(&GshT[h2][0]);          // rows 0-3 (broadcast)
        const float4 gb = *(const float4*)(&GshT[h2][4]);          // rows 4-7 (broadcast)
        ax[0] = fmaf(ga.x, w.x, ax[0]);  ay[0] = fmaf(ga.x, w.y, ay[0]);
        ax[1] = fmaf(ga.y, w.x, ax[1]);  ay[1] = fmaf(ga.y, w.y, ay[1]);
        ax[2] = fmaf(ga.z, w.x, ax[2]);  ay[2] = fmaf(ga.z, w.y, ay[2]);
        ax[3] = fmaf(ga.w, w.x, ax[3]);  ay[3] = fmaf(ga.w, w.y, ay[3]);
        ax[4] = fmaf(gb.x, w.x, ax[4]);  ay[4] = fmaf(gb.x, w.y, ay[4]);
        ax[5] = fmaf(gb.y, w.x, ax[5]);  ay[5] = fmaf(gb.y, w.y, ay[5]);
        ax[6] = fmaf(gb.z, w.x, ax[6]);  ay[6] = fmaf(gb.z, w.y, ay[6]);
        ax[7] = fmaf(gb.w, w.x, ax[7]);  ay[7] = fmaf(gb.w, w.y, ay[7]);
    }
    {
        const float2 bo = *(const float2*)(bo2 + d0);
        const float bb0 = (float)Q_SZ * bo.x;
        const float bb1 = (float)Q_SZ * bo.y;
        #pragma unroll
        for (int r = 0; r < ROWS; r++) { ax[r] += bb0; ay[r] += bb1; }
    }

    // LayerNorm reductions
    #pragma unroll
    for (int r = 0; r < ROWS; r++) {
        float ps = ax[r] + ay[r];
        float pq = ax[r] * ax[r] + ay[r] * ay[r];
        #pragma unroll
        for (int off = 16; off > 0; off >>= 1) {
            ps += __shfl_xor_sync(0xffffffffu, ps, off);
            pq += __shfl_xor_sync(0xffffffffu, pq, off);
        }
        if (lane == 0) { red[r][warp][0] = ps; red[r][warp][1] = pq; }
    }
    __syncthreads();

    const float2 gm = *(const float2*)(gamma + d0);
    const float2 bt = *(const float2*)(beta + d0);
    #pragma unroll
    for (int r = 0; r < ROWS; r++) {
        float s = 0.f, q2 = 0.f;
        #pragma unroll
        for (int w = 0; w < 8; w++) { s += red[r][w][0]; q2 += red[r][w][1]; }
        const float mu  = s * (1.f / (float)DOUT);
        const float var = q2 * (1.f / (float)DOUT) - mu * mu;
        const float inv = rsqrtf(var + EPS);
        float2 o;
        o.x = (ax[r] - mu) * inv * gm.x + bt.x;
        o.y = (ay[r] - mu) * inv * gm.y + bt.y;
        *(float2*)(out + base + (long)r * DOUT + d0) = o;
    }
}

// ---------------------------------------------------------------------------
// Launch
// ---------------------------------------------------------------------------
extern "C" void kernel_launch(void* const* d_in, const int* in_sizes, int n_in,
                              void* d_out, int out_size)
{
    const float* x     = (const float*)d_in[0];
    const float* wp    = (const float*)d_in[1];
    const float* bp    = (const float*)d_in[2];
    const float* wi1   = (const float*)d_in[3];
    const float* bi1   = (const float*)d_in[4];
    const float* wi2   = (const float*)d_in[5];
    const float* bi2   = (const float*)d_in[6];
    const float* wo1   = (const float*)d_in[7];
    const float* bo1   = (const float*)d_in[8];
    const float* wo2   = (const float*)d_in[9];
    const float* bo2   = (const float*)d_in[10];
    const float* gamma = (const float*)d_in[11];
    const float* beta  = (const float*)d_in[12];
    float* out = (float*)d_out;

    float* xp;             cudaGetSymbolAddress((void**)&xp, g_xp);
    __nv_bfloat16* Ab;     cudaGetSymbolAddress((void**)&Ab, g_A);
    __nv_bfloat16* Bb;     cudaGetSymbolAddress((void**)&Bb, g_Bt);

    conv_x<<<B_SZ, 256>>>(x, Ab);
    conv_w<<<dim3(DIN / 32, DOUT / 32), 256>>>(wp, Bb);

    const int dyn = GS * STAGEB + 1024;   // ~97 KB
    cudaFuncSetAttribute(gemm_tc, cudaFuncAttributeMaxDynamicSharedMemorySize, dyn);
    gemm_tc<<<dim3(DOUT / 128, B_SZ / 128, 2), 256, dyn>>>(Ab, Bb, xp);

    kan_fused<<<B_SZ / ROWS, 256>>>(xp, xp + (long)B_SZ * DOUT, bp,
                                    wi1, bi1, wi2, bi2,
                                    wo1, bo1, wo2, bo2, gamma, beta, out);
}

// round 7
// speedup vs baseline: 2.1758x; 1.0094x over previous
#include <cuda_runtime.h>
#include <cuda_bf16.h>
#include <cstdint>

// Problem constants
#define B_SZ   4096
#define DIN    768
#define DOUT   512
#define Q_SZ   64
#define H1_SZ  32
#define H2_SZ  64
#define EPS    1e-5f

// GEMM1 split-K: K' = 3 * DIN, split across 2 CTAs in z
#define KSPLIT (3 * DIN)          // 2304
#define KC     64
#define NCHH   (KSPLIT / KC / 2)  // 18 chunks per K-half
#define GS     3                  // pipeline stages
#define TILEB  16384              // one 128x64 bf16 tile
#define STAGEB (2 * TILEB)

// ---------------------------------------------------------------------------
// Static device scratch
// ---------------------------------------------------------------------------
__device__ __align__(256) float          g_xp[2][B_SZ * DOUT];          // 16 MB partials
__device__ __align__(256) __nv_bfloat16  g_A[B_SZ * KSPLIT];            // 18.9 MB
__device__ __align__(256) __nv_bfloat16  g_Bt[DOUT * KSPLIT];           // 2.36 MB

// ---------------------------------------------------------------------------
// Helpers
// ---------------------------------------------------------------------------
__device__ __forceinline__ uint32_t smem_u32(const void* p) {
    uint32_t a;
    asm("{ .reg .u64 t; cvta.to.shared.u64 t, %1; cvt.u32.u64 %0, t; }"
        : "=r"(a) : "l"(p));
    return a;
}
__device__ __forceinline__ uint32_t swz(uint32_t off) {
    return off ^ ((off >> 3) & 0x70);
}
__device__ __forceinline__ void cpasync16(uint32_t dst, const void* src) {
    asm volatile("cp.async.cg.shared.global [%0], [%1], 16;"
                 :: "r"(dst), "l"(src) : "memory");
}
__device__ __forceinline__ void ldsm_x4(uint32_t* r, uint32_t addr) {
    asm volatile("ldmatrix.sync.aligned.m8n8.x4.shared.b16 {%0,%1,%2,%3}, [%4];"
                 : "=r"(r[0]), "=r"(r[1]), "=r"(r[2]), "=r"(r[3]) : "r"(addr));
}
__device__ __forceinline__ void ldsm_x2(uint32_t* r, uint32_t addr) {
    asm volatile("ldmatrix.sync.aligned.m8n8.x2.shared.b16 {%0,%1}, [%2];"
                 : "=r"(r[0]), "=r"(r[1]) : "r"(addr));
}
__device__ __forceinline__ void mma16816(float* d, const uint32_t* a, const uint32_t* b) {
    asm volatile(
        "mma.sync.aligned.m16n8k16.row.col.f32.bf16.bf16.f32 "
        "{%0,%1,%2,%3}, {%4,%5,%6,%7}, {%8,%9}, {%0,%1,%2,%3};"
        : "+f"(d[0]), "+f"(d[1]), "+f"(d[2]), "+f"(d[3])
        : "r"(a[0]), "r"(a[1]), "r"(a[2]), "r"(a[3]), "r"(b[0]), "r"(b[1]));
}

// ---- packed f32x2 (Blackwell base PTX; FFMA2/FADD2 SASS) ----
__device__ __forceinline__ uint64_t pk2(float x, float y) {
    uint64_t r; asm("mov.b64 %0,{%1,%2};" : "=l"(r) : "f"(x), "f"(y)); return r;
}
__device__ __forceinline__ void upk2(uint64_t v, float& x, float& y) {
    asm("mov.b64 {%0,%1},%2;" : "=f"(x), "=f"(y) : "l"(v));
}
__device__ __forceinline__ uint64_t fma2(uint64_t a, uint64_t b, uint64_t c) {
    uint64_t d; asm("fma.rn.f32x2 %0,%1,%2,%3;" : "=l"(d) : "l"(a), "l"(b), "l"(c));
    return d;
}
__device__ __forceinline__ uint64_t add2(uint64_t a, uint64_t b) {
    uint64_t d; asm("add.rn.f32x2 %0,%1,%2;" : "=l"(d) : "l"(a), "l"(b));
    return d;
}
__device__ __forceinline__ uint64_t abs2(uint64_t a) {
    uint64_t d; asm("and.b64 %0,%1,0x7FFFFFFF7FFFFFFF;" : "=l"(d) : "l"(a));
    return d;
}

// ---------------------------------------------------------------------------
// Conversions (fp32 -> bf16 hi/lo, 3-term fold into K)
// ---------------------------------------------------------------------------
__global__ void __launch_bounds__(256)
conv_x(const float* __restrict__ x, __nv_bfloat16* __restrict__ A)
{
    const int row = blockIdx.x;
    const float* xr = x + (long)row * DIN;
    __nv_bfloat16* Ar = A + (long)row * KSPLIT;
    #pragma unroll
    for (int i = 0; i < 3; i++) {
        const int k = threadIdx.x + i * 256;
        const float v = xr[k];
        const __nv_bfloat16 hi = __float2bfloat16(v);
        const __nv_bfloat16 lo = __float2bfloat16(v - __bfloat162float(hi));
        Ar[k]            = hi;
        Ar[k + DIN]      = hi;
        Ar[k + 2 * DIN]  = lo;
    }
}

__global__ void __launch_bounds__(256)
conv_w(const float* __restrict__ wp, __nv_bfloat16* __restrict__ Bt)
{
    __shared__ float t[32][33];
    const int k0 = blockIdx.x * 32, n0 = blockIdx.y * 32;
    const int tx = threadIdx.x & 31;
    const int ty = threadIdx.x >> 5;
    #pragma unroll
    for (int dy = 0; dy < 32; dy += 8)
        t[ty + dy][tx] = wp[(long)(k0 + ty + dy) * DOUT + n0 + tx];
    __syncthreads();
    #pragma unroll
    for (int dy = 0; dy < 32; dy += 8) {
        const int n = n0 + ty + dy, k = k0 + tx;
        const float v = t[tx][ty + dy];
        const __nv_bfloat16 hi = __float2bfloat16(v);
        const __nv_bfloat16 lo = __float2bfloat16(v - __bfloat162float(hi));
        __nv_bfloat16* Br = Bt + (long)n * KSPLIT;
        Br[k]           = hi;
        Br[k + DIN]     = lo;
        Br[k + 2 * DIN] = hi;
    }
}

// ---------------------------------------------------------------------------
// GEMM1, split-K=2 (unchanged from R6, passing)
// ---------------------------------------------------------------------------
__global__ void __launch_bounds__(256, 2)
gemm_tc(const __nv_bfloat16* __restrict__ Ag, const __nv_bfloat16* __restrict__ Bg,
        float* __restrict__ Cbase)
{
    extern __shared__ char dynsmem[];

    const int tid  = threadIdx.x;
    const int warp = tid >> 5, lane = tid & 31;
    const int wm = warp >> 2;
    const int wn = warp & 3;
    const int bn = blockIdx.x, bm = blockIdx.y, kz = blockIdx.z;

    const uint32_t abase = (smem_u32(dynsmem) + 1023u) & ~1023u;

    const __nv_bfloat16* Atile = Ag + (long)(bm * 128) * KSPLIT;
    const __nv_bfloat16* Btile = Bg + (long)(bn * 128) * KSPLIT;
    float* C = Cbase + (long)kz * (B_SZ * DOUT);
    const int kbase = kz * (NCHH * KC);

    auto load_chunk = [&](int c, int s) {
        const uint32_t sa = abase + s * STAGEB;
        const uint32_t sb = sa + TILEB;
        const int koff = kbase + c * KC;
        #pragma unroll
        for (int it = 0; it < 4; it++) {
            const int idx = it * 256 + tid;
            const int row = idx >> 3;
            const int c16 = idx & 7;
            const uint32_t soff = swz(row * 128 + c16 * 16);
            cpasync16(sa + soff, Atile + (long)row * KSPLIT + koff + c16 * 8);
            cpasync16(sb + soff, Btile + (long)row * KSPLIT + koff + c16 * 8);
        }
        asm volatile("cp.async.commit_group;" ::: "memory");
    };

    float acc[4][4][4];
    #pragma unroll
    for (int mt = 0; mt < 4; mt++)
        #pragma unroll
        for (int nt = 0; nt < 4; nt++)
            #pragma unroll
            for (int j = 0; j < 4; j++) acc[mt][nt][j] = 0.f;

    const uint32_t a_row = wm * 64 + (lane & 15);
    const uint32_t a_seg = (lane >> 4) * 16;
    const uint32_t b_row = wn * 32 + (lane & 7);
    const uint32_t b_seg = ((lane >> 3) & 1) * 16;

    load_chunk(0, 0);
    load_chunk(1, 1);

    int s_cons = 0, s_load = 2;
    for (int c = 0; c < NCHH; c++) {
        asm volatile("cp.async.wait_group %0;" :: "n"(GS - 2) : "memory");
        __syncthreads();

        const int nl = c + GS - 1;
        if (nl < NCHH) load_chunk(nl, s_load);
        if (++s_load == GS) s_load = 0;

        const uint32_t sa = abase + s_cons * STAGEB;
        const uint32_t sb = sa + TILEB;
        if (++s_cons == GS) s_cons = 0;

        #pragma unroll
        for (int ks = 0; ks < 4; ks++) {
            uint32_t bf[4][2];
            #pragma unroll
            for (int nt = 0; nt < 4; nt++)
                ldsm_x2(bf[nt], sb + swz((b_row + nt * 8) * 128 + ks * 32 + b_seg));
            #pragma unroll
            for (int mt = 0; mt < 4; mt++) {
                uint32_t af[4];
                ldsm_x4(af, sa + swz((a_row + mt * 16) * 128 + ks * 32 + a_seg));
                #pragma unroll
                for (int nt = 0; nt < 4; nt++)
                    mma16816(acc[mt][nt], af, bf[nt]);
            }
        }
    }

    const int g  = lane >> 2;
    const int tg = lane & 3;
    #pragma unroll
    for (int mt = 0; mt < 4; mt++) {
        const int m = bm * 128 + wm * 64 + mt * 16 + g;
        #pragma unroll
        for (int nt = 0; nt < 4; nt++) {
            const int n = bn * 128 + wn * 32 + nt * 8 + 2 * tg;
            float2 v0, v1;
            v0.x = acc[mt][nt][0];  v0.y = acc[mt][nt][1];
            v1.x = acc[mt][nt][2];  v1.y = acc[mt][nt][3];
            *(float2*)(C + (long)m * DOUT + n)       = v0;
            *(float2*)(C + (long)(m + 8) * DOUT + n) = v1;
        }
    }
}

// ---------------------------------------------------------------------------
// Kernel 2: fused  (p0+p1+bias) -> S -> u -> G -> (G@wo2 + Q*bo2) -> LayerNorm
// Stages B and E use packed f32x2 FMA (FFMA2) to halve fma-pipe traffic.
// ---------------------------------------------------------------------------
#define ROWS 8

__global__ void __launch_bounds__(256)
kan_fused(const float* __restrict__ xp0, const float* __restrict__ xp1,
          const float* __restrict__ bp,
          const float* __restrict__ wi1, const float* __restrict__ bi1,
          const float* __restrict__ wi2, const float* __restrict__ bi2,
          const float* __restrict__ wo1, const float* __restrict__ bo1,
          const float* __restrict__ wo2, const float* __restrict__ bo2,
          const float* __restrict__ gamma, const float* __restrict__ beta,
          float* __restrict__ out)
{
    __shared__ float rows[ROWS][DOUT];
    __shared__ float Ssh[ROWS][H1_SZ];
    __shared__ float ush[ROWS][Q_SZ];
    __shared__ float GshT[H2_SZ][ROWS];     // transposed: [h2][r]
    __shared__ float red[ROWS][8][2];

    const int tid  = threadIdx.x;
    const int warp = tid >> 5;
    const int lane = tid & 31;
    const long base = (long)blockIdx.x * ROWS * DOUT;

    // Load 8 rows: xp0 + xp1 + bias
    {
        const float4* s0 = (const float4*)(xp0 + base);
        const float4* s1 = (const float4*)(xp1 + base);
        const float4* bb = (const float4*)bp;
        float4* dst = (float4*)(&rows[0][0]);
        #pragma unroll
        for (int i = 0; i < 4; i++) {
            const int j = tid + i * 256;
            const float4 a = s0[j];
            const float4 b = s1[j];
            const float4 c = bb[j & 127];
            float4 o;
            o.x = a.x + b.x + c.x;
            o.y = a.y + b.y + c.y;
            o.z = a.z + b.z + c.z;
            o.w = a.w + b.w + c.w;
            dst[j] = o;
        }
    }
    __syncthreads();

    // Stage B: S = 0.5*(w*V + 512*b + sum|v*w+b|)   (packed f32x2)
    {
        const float4* rv = (const float4*)(&rows[warp][0]);

        // per-row sum V (packed adds, then shfl reduce)
        uint64_t vp = pk2(0.f, 0.f);
        #pragma unroll
        for (int i = 0; i < 4; i++) {
            const float4 v = rv[lane + i * 32];
            vp = add2(vp, pk2(v.x, v.y));
            vp = add2(vp, pk2(v.z, v.w));
        }
        float va, vb; upk2(vp, va, vb);
        float vs = va + vb;
        #pragma unroll
        for (int off = 16; off > 0; off >>= 1)
            vs += __shfl_xor_sync(0xffffffffu, vs, off);

        const float w1 = wi1[lane];
        const float b1 = bi1[lane];
        const uint64_t w11 = pk2(w1, w1);
        const uint64_t b11 = pk2(b1, b1);
        uint64_t s01 = pk2(0.f, 0.f), s23 = pk2(0.f, 0.f);
        #pragma unroll 4
        for (int d4 = 0; d4 < DOUT / 4; d4++) {
            const float4 v = rv[d4];
            s01 = add2(s01, abs2(fma2(pk2(v.x, v.y), w11, b11)));
            s23 = add2(s23, abs2(fma2(pk2(v.z, v.w), w11, b11)));
        }
        float a0, a1, a2, a3;
        upk2(s01, a0, a1); upk2(s23, a2, a3);
        const float sabs = (a0 + a1) + (a2 + a3);
        Ssh[warp][lane] = 0.5f * (fmaf(w1, vs, (float)DOUT * b1) + sabs);
    }
    __syncthreads();

    // Stage C: u[r][q]
    #pragma unroll
    for (int it = 0; it < 2; it++) {
        const int idx = tid + it * 256;
        const int r = idx >> 6, q = idx & 63;
        float acc = (float)DOUT * bi2[q];
        #pragma unroll
        for (int h = 0; h < H1_SZ; h++)
            acc = fmaf(Ssh[r][h], wi2[h * Q_SZ + q], acc);
        ush[r][q] = acc;
    }
    __syncthreads();

    // Stage D: G[r][h2] -> stored transposed
    #pragma unroll
    for (int it = 0; it < 2; it++) {
        const int idx = tid + it * 256;
        const int r = idx >> 6, h2 = idx & 63;
        const float w = wo1[h2];
        const float b = bo1[h2];
        float g = 0.f;
        #pragma unroll
        for (int q = 0; q < Q_SZ; q++)
            g += fmaxf(fmaf(ush[r][q], w, b), 0.f);
        GshT[h2][r] = g;
    }
    __syncthreads();

    // Stage E (packed f32x2): accumulators packed over ROW PAIRS so G pairs
    // come straight out of the float4 broadcast loads.
    // acc2[c*4+p] = cols d0+c, rows (2p, 2p+1)
    const int d0 = tid * 2;
    uint64_t acc2[8];
    #pragma unroll
    for (int j = 0; j < 8; j++) acc2[j] = pk2(0.f, 0.f);

    #pragma unroll 4
    for (int h2 = 0; h2 < H2_SZ; h2++) {
        const float2 w = *(const float2*)(wo2 + h2 * DOUT + d0);   // LDG.64 coalesced
        const uint64_t wx = pk2(w.x, w.x);
        const uint64_t wy = pk2(w.y, w.y);
        const float4 ga = *(const float4*)(&GshT[h2][0]);          // rows 0-3 (broadcast)
        const float4 gb = *(const float4*)(&GshT[h2][4]);          // rows 4-7 (broadcast)
        const uint64_t g01 = pk2(ga.x, ga.y);
        const uint64_t g23 = pk2(ga.z, ga.w);
        const uint64_t g45 = pk2(gb.x, gb.y);
        const uint64_t g67 = pk2(gb.z, gb.w);
        acc2[0] = fma2(g01, wx, acc2[0]);
        acc2[1] = fma2(g23, wx, acc2[1]);
        acc2[2] = fma2(g45, wx, acc2[2]);
        acc2[3] = fma2(g67, wx, acc2[3]);
        acc2[4] = fma2(g01, wy, acc2[4]);
        acc2[5] = fma2(g23, wy, acc2[5]);
        acc2[6] = fma2(g45, wy, acc2[6]);
        acc2[7] = fma2(g67, wy, acc2[7]);
    }

    float ax[ROWS], ay[ROWS];
    {
        const float2 bo = *(const float2*)(bo2 + d0);
        const uint64_t bbx = pk2((float)Q_SZ * bo.x, (float)Q_SZ * bo.x);
        const uint64_t bby = pk2((float)Q_SZ * bo.y, (float)Q_SZ * bo.y);
        #pragma unroll
        for (int p = 0; p < 4; p++) {
            acc2[p]     = add2(acc2[p], bbx);
            acc2[4 + p] = add2(acc2[4 + p], bby);
            upk2(acc2[p],     ax[2 * p], ax[2 * p + 1]);
            upk2(acc2[4 + p], ay[2 * p], ay[2 * p + 1]);
        }
    }

    // LayerNorm reductions
    #pragma unroll
    for (int r = 0; r < ROWS; r++) {
        float ps = ax[r] + ay[r];
        float pq = ax[r] * ax[r] + ay[r] * ay[r];
        #pragma unroll
        for (int off = 16; off > 0; off >>= 1) {
            ps += __shfl_xor_sync(0xffffffffu, ps, off);
            pq += __shfl_xor_sync(0xffffffffu, pq, off);
        }
        if (lane == 0) { red[r][warp][0] = ps; red[r][warp][1] = pq; }
    }
    __syncthreads();

    const float2 gm = *(const float2*)(gamma + d0);
    const float2 bt = *(const float2*)(beta + d0);
    #pragma unroll
    for (int r = 0; r < ROWS; r++) {
        float s = 0.f, q2 = 0.f;
        #pragma unroll
        for (int w = 0; w < 8; w++) { s += red[r][w][0]; q2 += red[r][w][1]; }
        const float mu  = s * (1.f / (float)DOUT);
        const float var = q2 * (1.f / (float)DOUT) - mu * mu;
        const float inv = rsqrtf(var + EPS);
        float2 o;
        o.x = (ax[r] - mu) * inv * gm.x + bt.x;
        o.y = (ay[r] - mu) * inv * gm.y + bt.y;
        *(float2*)(out + base + (long)r * DOUT + d0) = o;
    }
}

// ---------------------------------------------------------------------------
// Launch
// ---------------------------------------------------------------------------
extern "C" void kernel_launch(void* const* d_in, const int* in_sizes, int n_in,
                              void* d_out, int out_size)
{
    const float* x     = (const float*)d_in[0];
    const float* wp    = (const float*)d_in[1];
    const float* bp    = (const float*)d_in[2];
    const float* wi1   = (const float*)d_in[3];
    const float* bi1   = (const float*)d_in[4];
    const float* wi2   = (const float*)d_in[5];
    const float* bi2   = (const float*)d_in[6];
    const float* wo1   = (const float*)d_in[7];
    const float* bo1   = (const float*)d_in[8];
    const float* wo2   = (const float*)d_in[9];
    const float* bo2   = (const float*)d_in[10];
    const float* gamma = (const float*)d_in[11];
    const float* beta  = (const float*)d_in[12];
    float* out = (float*)d_out;

    float* xp;             cudaGetSymbolAddress((void**)&xp, g_xp);
    __nv_bfloat16* Ab;     cudaGetSymbolAddress((void**)&Ab, g_A);
    __nv_bfloat16* Bb;     cudaGetSymbolAddress((void**)&Bb, g_Bt);

    conv_x<<<B_SZ, 256>>>(x, Ab);
    conv_w<<<dim3(DIN / 32, DOUT / 32), 256>>>(wp, Bb);

    const int dyn = GS * STAGEB + 1024;   // ~97 KB
    cudaFuncSetAttribute(gemm_tc, cudaFuncAttributeMaxDynamicSharedMemorySize, dyn);
    gemm_tc<<<dim3(DOUT / 128, B_SZ / 128, 2), 256, dyn>>>(Ab, Bb, xp);

    kan_fused<<<B_SZ / ROWS, 256>>>(xp, xp + (long)B_SZ * DOUT, bp,
                                    wi1, bi1, wi2, bi2,
                                    wo1, bo1, wo2, bo2, gamma, beta, out);
}